// round 6
// baseline (speedup 1.0000x reference)
#include <cuda_runtime.h>
#include <math.h>

#define NN   50000
#define NE   800000
#define IND  64
#define HID  192
#define NH   12
#define NL   3
#define EPSF 1e-5f
#define TM   16               // nodes per tile (inproj/gate)
#define TG   25               // nodes per tile (gemm2)
#define NB   49               // scan blocks (ceil(NN/1024))
#define CH   32               // aggregation chunk (edges)

// ---------------- scratch (static device globals; no allocation) ----------------
__device__ float  d_h    [NN * HID];
__device__ float  d_xl   [NN * HID];
__device__ float  d_xr   [NN * HID];
__device__ float  d_tmp  [NN * HID];
__device__ int    d_deg  [NN];
__device__ int    d_fill [NN];
__device__ int    d_rows [NN + 1];
__device__ int    d_bsum [NB];
__device__ int    d_boff [NB];
__device__ int    d_csrc [NE];
__device__ int    d_cdst [NE];
__device__ float2 d_cea  [NE];
__device__ float  d_s    [(size_t)NE * NH];
__device__ float  d_sself[NN * NH];
__device__ float  d_suma [NN * 2];
__device__ float  d_ma   [NN * 2];

// ---------------- f32x2 packed helpers ----------------
typedef unsigned long long u64t;
__device__ __forceinline__ void ffma2(u64t& d, u64t a, u64t b) {
    asm("fma.rn.f32x2 %0, %1, %2, %0;" : "+l"(d) : "l"(a), "l"(b));
}
__device__ __forceinline__ u64t pack2(float lo, float hi) {
    u64t r; asm("mov.b64 %0, {%1, %2};" : "=l"(r) : "f"(lo), "f"(hi)); return r;
}
__device__ __forceinline__ float unpack_sum(u64t v) {
    float lo, hi; asm("mov.b64 {%0, %1}, %2;" : "=f"(lo), "=f"(hi) : "l"(v));
    return lo + hi;
}

// block-wide mean/rstd over 192 values (6 warps)
__device__ __forceinline__ void blockStats192(float v, float& mean, float& rstd) {
    __shared__ float red[14];
    float s = v, s2 = v * v;
    #pragma unroll
    for (int o = 16; o; o >>= 1) {
        s  += __shfl_xor_sync(0xffffffffu, s,  o);
        s2 += __shfl_xor_sync(0xffffffffu, s2, o);
    }
    int w = threadIdx.x >> 5;
    if ((threadIdx.x & 31) == 0) { red[w] = s; red[7 + w] = s2; }
    __syncthreads();
    if (threadIdx.x == 0) {
        float ts = 0.f, t2 = 0.f;
        #pragma unroll
        for (int i = 0; i < 6; i++) { ts += red[i]; t2 += red[7 + i]; }
        float m   = ts * (1.f / HID);
        float var = t2 * (1.f / HID) - m * m;
        red[6]  = m;
        red[13] = rsqrtf(var + EPSF);
    }
    __syncthreads();
    mean = red[6];
    rstd = red[13];
}

// ---------------- CSR build ----------------
__global__ void k_zero() {
    int i = blockIdx.x * blockDim.x + threadIdx.x;
    if (i < NN) { d_deg[i] = 0; d_fill[i] = 0; }
    if (i < 2 * NN) d_suma[i] = 0.f;
}

__global__ void k_hist(const int* __restrict__ ei, const float* __restrict__ eattr) {
    int e = blockIdx.x * blockDim.x + threadIdx.x;
    if (e >= NE) return;
    int dst = ei[NE + e];
    atomicAdd(&d_deg[dst], 1);
    atomicAdd(&d_suma[2 * dst    ], eattr[2 * e    ]);
    atomicAdd(&d_suma[2 * dst + 1], eattr[2 * e + 1]);
}

__global__ void k_mean() {
    int n = blockIdx.x * blockDim.x + threadIdx.x;
    if (n >= NN) return;
    float c = fmaxf((float)d_deg[n], 1.f);
    d_ma[2 * n    ] = d_suma[2 * n    ] / c;
    d_ma[2 * n + 1] = d_suma[2 * n + 1] / c;
}

__global__ void k_scanA() {
    __shared__ int wsum[32];
    int i = blockIdx.x * 1024 + threadIdx.x;
    int lane = threadIdx.x & 31, w = threadIdx.x >> 5;
    int v = (i < NN) ? d_deg[i] : 0;
    int sv = v;
    #pragma unroll
    for (int o = 1; o < 32; o <<= 1) {
        int u = __shfl_up_sync(0xffffffffu, sv, o);
        if (lane >= o) sv += u;
    }
    if (lane == 31) wsum[w] = sv;
    __syncthreads();
    if (w == 0) {
        int x = wsum[lane];
        #pragma unroll
        for (int o = 1; o < 32; o <<= 1) {
            int u = __shfl_up_sync(0xffffffffu, x, o);
            if (lane >= o) x += u;
        }
        wsum[lane] = x;
    }
    __syncthreads();
    int add = (w > 0) ? wsum[w - 1] : 0;
    if (i < NN) d_rows[i + 1] = add + sv;
    if (threadIdx.x == 1023) d_bsum[blockIdx.x] = add + sv;
}

__global__ void k_scanB() {
    __shared__ int s[NB];
    int t = threadIdx.x;
    if (t < NB) s[t] = d_bsum[t];
    __syncthreads();
    if (t == 0) {
        int run = 0;
        for (int i = 0; i < NB; i++) { int v = s[i]; s[i] = run; run += v; }
    }
    __syncthreads();
    if (t < NB) d_boff[t] = s[t];
}

__global__ void k_scanC() {
    int i = blockIdx.x * 1024 + threadIdx.x;
    if (i < NN) d_rows[i + 1] += d_boff[blockIdx.x];
    if (i == 0) d_rows[0] = 0;
}

__global__ void k_scatter(const int* __restrict__ ei, const float* __restrict__ eattr) {
    int e = blockIdx.x * blockDim.x + threadIdx.x;
    if (e >= NE) return;
    int dst = ei[NE + e];
    int pos = d_rows[dst] + atomicAdd(&d_fill[dst], 1);
    d_csrc[pos] = ei[e];
    d_cdst[pos] = dst;
    d_cea[pos]  = make_float2(eattr[2 * e], eattr[2 * e + 1]);
}

// ---------------- input projection: x@W_in + b, GELU -> d_tmp ----------------
__global__ void k_inproj(const float* __restrict__ x, const float* __restrict__ W,
                         const float* __restrict__ b) {
    __shared__ float sx[TM * IND];
    int base = blockIdx.x * TM;
    int j = threadIdx.x;
    {
        const float4* src = (const float4*)&x[(size_t)base * IND];
        float4* dstv = (float4*)sx;
        for (int i = j; i < TM * IND / 4; i += HID) dstv[i] = src[i];
    }
    __syncthreads();
    u64t acc2[TM];
    #pragma unroll
    for (int m = 0; m < TM; m++) acc2[m] = 0ull;
    for (int k = 0; k < IND; k += 4) {
        float w0 = W[(k + 0) * HID + j], w1 = W[(k + 1) * HID + j];
        float w2 = W[(k + 2) * HID + j], w3 = W[(k + 3) * HID + j];
        u64t wp01 = pack2(w0, w1), wp23 = pack2(w2, w3);
        #pragma unroll
        for (int m = 0; m < TM; m++) {
            ulonglong2 hp = *(const ulonglong2*)&sx[m * IND + k];
            ffma2(acc2[m], hp.x, wp01);
            ffma2(acc2[m], hp.y, wp23);
        }
    }
    float bj = b[j];
    #pragma unroll
    for (int m = 0; m < TM; m++) {
        float v = unpack_sum(acc2[m]) + bj;
        d_tmp[(size_t)(base + m) * HID + j] = v * normcdff(v);   // exact GELU
    }
}

// ---------------- LayerNorm: out = LN(in)*g + b ----------------
__global__ void k_ln(const float* __restrict__ in, const float* __restrict__ g,
                     const float* __restrict__ b, float* __restrict__ out) {
    int n = blockIdx.x, j = threadIdx.x;
    float v = in[(size_t)n * HID + j];
    float m, r; blockStats192(v, m, r);
    out[(size_t)n * HID + j] = (v - m) * r * g[j] + b[j];
}

// ---------------- dual GEMM: xl = h@Wl+bl, xr = h@Wr+br (f32x2 packed) ----------------
__global__ void k_gemm2(const float* __restrict__ Wl, const float* __restrict__ bl,
                        const float* __restrict__ Wr, const float* __restrict__ br) {
    __shared__ float sh[TG * HID];
    int base = blockIdx.x * TG;
    int j = threadIdx.x;
    {
        const float4* src = (const float4*)&d_h[(size_t)base * HID];
        float4* dstv = (float4*)sh;
        for (int i = j; i < TG * HID / 4; i += HID) dstv[i] = src[i];
    }
    __syncthreads();
    u64t al2[TG], ar2[TG];
    #pragma unroll
    for (int m = 0; m < TG; m++) { al2[m] = 0ull; ar2[m] = 0ull; }
    for (int k = 0; k < HID; k += 4) {
        float wl0 = Wl[(k + 0) * HID + j], wl1 = Wl[(k + 1) * HID + j];
        float wl2 = Wl[(k + 2) * HID + j], wl3 = Wl[(k + 3) * HID + j];
        float wr0 = Wr[(k + 0) * HID + j], wr1 = Wr[(k + 1) * HID + j];
        float wr2 = Wr[(k + 2) * HID + j], wr3 = Wr[(k + 3) * HID + j];
        u64t wlp01 = pack2(wl0, wl1), wlp23 = pack2(wl2, wl3);
        u64t wrp01 = pack2(wr0, wr1), wrp23 = pack2(wr2, wr3);
        #pragma unroll
        for (int m = 0; m < TG; m++) {
            ulonglong2 hp = *(const ulonglong2*)&sh[m * HID + k];
            ffma2(al2[m], hp.x, wlp01);
            ffma2(al2[m], hp.y, wlp23);
            ffma2(ar2[m], hp.x, wrp01);
            ffma2(ar2[m], hp.y, wrp23);
        }
    }
    float blj = bl[j], brj = br[j];
    #pragma unroll
    for (int m = 0; m < TG; m++) {
        d_xl[(size_t)(base + m) * HID + j] = unpack_sum(al2[m]) + blj;
        d_xr[(size_t)(base + m) * HID + j] = unpack_sum(ar2[m]) + brj;
    }
}

// ---------------- edge-parallel score kernel: one thread per (CSR edge, head) ----------------
__global__ void k_escore(const float* __restrict__ We, const float* __restrict__ att) {
    __shared__ float sW0[HID], sW1[HID], sA[HID];
    for (int i = threadIdx.x; i < HID; i += blockDim.x) {
        sW0[i] = We[i]; sW1[i] = We[HID + i]; sA[i] = att[i];
    }
    __syncthreads();
    int t = blockIdx.x * blockDim.x + threadIdx.x;
    const int total = (NE + NN) * NH;
    if (t >= total) return;
    int p = t / NH, h = t - p * NH;
    int src, dst; float ea0, ea1; float* sout;
    if (p < NE) {
        src = d_csrc[p]; dst = d_cdst[p];
        float2 ea = d_cea[p]; ea0 = ea.x; ea1 = ea.y;
        sout = &d_s[(size_t)p * NH + h];
    } else {
        int n = p - NE; src = dst = n;
        ea0 = d_ma[2 * n]; ea1 = d_ma[2 * n + 1];
        sout = &d_sself[n * NH + h];
    }
    const float4* pl = (const float4*)&d_xl[(size_t)src * HID + h * 16];
    const float4* pr = (const float4*)&d_xr[(size_t)dst * HID + h * 16];
    float s = 0.f;
    #pragma unroll
    for (int i = 0; i < 4; i++) {
        float4 a = pl[i], bq = pr[i];
        int jb = h * 16 + i * 4;
        float m0 = a.x + bq.x + ea0 * sW0[jb + 0] + ea1 * sW1[jb + 0];
        float m1 = a.y + bq.y + ea0 * sW0[jb + 1] + ea1 * sW1[jb + 1];
        float m2 = a.z + bq.z + ea0 * sW0[jb + 2] + ea1 * sW1[jb + 2];
        float m3 = a.w + bq.w + ea0 * sW0[jb + 3] + ea1 * sW1[jb + 3];
        m0 = m0 > 0.f ? m0 : 0.2f * m0;
        m1 = m1 > 0.f ? m1 : 0.2f * m1;
        m2 = m2 > 0.f ? m2 : 0.2f * m2;
        m3 = m3 > 0.f ? m3 : 0.2f * m3;
        s += m0 * sA[jb + 0] + m1 * sA[jb + 1] + m2 * sA[jb + 2] + m3 * sA[jb + 3];
    }
    *sout = s;
}

// ---------------- per-node: softmax normalize + aggregate + residual + LN ----------------
__global__ void k_node2(const float* __restrict__ bo, const float* __restrict__ g,
                        const float* __restrict__ b) {
    __shared__ float s_max[NH], s_invden[NH];
    __shared__ float s_alpha[CH * NH];
    __shared__ int   s_src[CH];
    int n = blockIdx.x, j = threadIdx.x, hj = j >> 4;
    int row = d_rows[n];
    int deg = d_rows[n + 1] - row;

    // 12 threads: per-head max & denominator over self + CSR strip
    if (j < NH) {
        float self_s = d_sself[n * NH + j];
        const float* sp = &d_s[(size_t)row * NH + j];
        float m = self_s;
        int p = 0;
        for (; p + 4 <= deg; p += 4) {
            float v0 = sp[(p + 0) * NH], v1 = sp[(p + 1) * NH];
            float v2 = sp[(p + 2) * NH], v3 = sp[(p + 3) * NH];
            m = fmaxf(m, fmaxf(fmaxf(v0, v1), fmaxf(v2, v3)));
        }
        for (; p < deg; p++) m = fmaxf(m, sp[p * NH]);
        float den = __expf(self_s - m);
        p = 0;
        for (; p + 4 <= deg; p += 4) {
            den += __expf(sp[(p + 0) * NH] - m) + __expf(sp[(p + 1) * NH] - m)
                 + __expf(sp[(p + 2) * NH] - m) + __expf(sp[(p + 3) * NH] - m);
        }
        for (; p < deg; p++) den += __expf(sp[p * NH] - m);
        s_max[j] = m;
        s_invden[j] = 1.f / den;
    }
    __syncthreads();

    float mh = s_max[hj];
    float xl_self = d_xl[(size_t)n * HID + j];
    float acc = __expf(d_sself[n * NH + hj] - mh) * xl_self;

    for (int base = 0; base < deg; base += CH) {
        int m = min(CH, deg - base);
        // stage alphas + src indices in smem
        for (int idx = j; idx < m * NH; idx += HID) {
            int pp = idx / NH, hh = idx - pp * NH;
            s_alpha[idx] = __expf(d_s[(size_t)(row + base + pp) * NH + hh] - s_max[hh]);
        }
        if (j < m) s_src[j] = d_csrc[row + base + j];
        __syncthreads();
        int p = 0;
        for (; p + 4 <= m; p += 4) {
            int i0 = s_src[p], i1 = s_src[p + 1], i2 = s_src[p + 2], i3 = s_src[p + 3];
            float a0 = s_alpha[(p + 0) * NH + hj];
            float a1 = s_alpha[(p + 1) * NH + hj];
            float a2 = s_alpha[(p + 2) * NH + hj];
            float a3 = s_alpha[(p + 3) * NH + hj];
            float x0 = d_xl[(size_t)i0 * HID + j];
            float x1 = d_xl[(size_t)i1 * HID + j];
            float x2 = d_xl[(size_t)i2 * HID + j];
            float x3 = d_xl[(size_t)i3 * HID + j];
            acc = fmaf(a0, x0, acc);
            acc = fmaf(a1, x1, acc);
            acc = fmaf(a2, x2, acc);
            acc = fmaf(a3, x3, acc);
        }
        for (; p < m; p++) {
            acc = fmaf(s_alpha[p * NH + hj], d_xl[(size_t)s_src[p] * HID + j], acc);
        }
        __syncthreads();
    }

    float v = d_h[(size_t)n * HID + j] + acc * s_invden[hj] + bo[j];
    float mean, rstd; blockStats192(v, mean, rstd);
    d_h[(size_t)n * HID + j] = (v - mean) * rstd * g[j] + b[j];
}

// ---------------- gate: d_tmp = h * sigmoid(h@Wg + bg) ----------------
__global__ void k_gate(const float* __restrict__ Wg, const float* __restrict__ bg) {
    __shared__ float sh[TM * HID];
    int base = blockIdx.x * TM;
    int j = threadIdx.x;
    {
        const float4* src = (const float4*)&d_h[(size_t)base * HID];
        float4* dstv = (float4*)sh;
        for (int i = j; i < TM * HID / 4; i += HID) dstv[i] = src[i];
    }
    __syncthreads();
    u64t acc2[TM];
    #pragma unroll
    for (int m = 0; m < TM; m++) acc2[m] = 0ull;
    for (int k = 0; k < HID; k += 4) {
        float w0 = Wg[(k + 0) * HID + j], w1 = Wg[(k + 1) * HID + j];
        float w2 = Wg[(k + 2) * HID + j], w3 = Wg[(k + 3) * HID + j];
        u64t wp01 = pack2(w0, w1), wp23 = pack2(w2, w3);
        #pragma unroll
        for (int m = 0; m < TM; m++) {
            ulonglong2 hp = *(const ulonglong2*)&sh[m * HID + k];
            ffma2(acc2[m], hp.x, wp01);
            ffma2(acc2[m], hp.y, wp23);
        }
    }
    float bj = bg[j];
    #pragma unroll
    for (int m = 0; m < TM; m++) {
        float gsig = 1.f / (1.f + __expf(-(unpack_sum(acc2[m]) + bj)));
        d_tmp[(size_t)(base + m) * HID + j] = sh[m * HID + j] * gsig;
    }
}

// ---------------- launcher ----------------
extern "C" void kernel_launch(void* const* d_in, const int* in_sizes, int n_in,
                              void* d_out, int out_size) {
    const float* x     = (const float*)d_in[0];
    const int*   ei    = (const int*)  d_in[1];
    const float* eattr = (const float*)d_in[2];
    const float* Win   = (const float*)d_in[3];
    const float* b_in  = (const float*)d_in[4];
    const float* g_lni = (const float*)d_in[5];
    const float* b_lni = (const float*)d_in[6];
    const float* Wl    = (const float*)d_in[7];
    const float* bl    = (const float*)d_in[8];
    const float* Wr    = (const float*)d_in[9];
    const float* br    = (const float*)d_in[10];
    const float* We    = (const float*)d_in[11];
    const float* att   = (const float*)d_in[12];
    const float* bo    = (const float*)d_in[13];
    const float* g_res = (const float*)d_in[14];
    const float* b_res = (const float*)d_in[15];
    const float* Wg    = (const float*)d_in[16];
    const float* bg    = (const float*)d_in[17];
    const float* g_f   = (const float*)d_in[18];
    const float* b_f   = (const float*)d_in[19];
    float* out = (float*)d_out;

    float *p_tmp, *p_h;
    cudaGetSymbolAddress((void**)&p_tmp, d_tmp);
    cudaGetSymbolAddress((void**)&p_h,   d_h);

    // CSR build + self-loop mean edge_attr
    k_zero<<<(2 * NN + 255) / 256, 256>>>();
    k_hist<<<(NE + 255) / 256, 256>>>(ei, eattr);
    k_mean<<<(NN + 255) / 256, 256>>>();
    k_scanA<<<NB, 1024>>>();
    k_scanB<<<1, 64>>>();
    k_scanC<<<NB, 1024>>>();
    k_scatter<<<(NE + 255) / 256, 256>>>(ei, eattr);

    // input projection + GELU + LN -> d_h
    k_inproj<<<NN / TM, HID>>>(x, Win, b_in);
    k_ln<<<NN, HID>>>(p_tmp, g_lni, b_lni, p_h);

    const int ESG = ((NE + NN) * NH + 255) / 256;
    for (int l = 0; l < NL; l++) {
        k_gemm2<<<NN / TG, HID>>>(Wl + (size_t)l * HID * HID, bl + l * HID,
                                  Wr + (size_t)l * HID * HID, br + l * HID);
        k_escore<<<ESG, 256>>>(We + (size_t)l * 2 * HID, att + (size_t)l * HID);
        k_node2<<<NN, HID>>>(bo + l * HID, g_res + l * HID, b_res + l * HID);
    }

    k_gate<<<NN / TM, HID>>>(Wg, bg);
    k_ln<<<NN, HID>>>(p_tmp, g_f, b_f, out);
}